// round 15
// baseline (speedup 1.0000x reference)
#include <cuda_runtime.h>

// Black_oil PINO residual, GB300 sm_103a — float4 over y.
// FINAL (= R8, best: 29.2us / DRAM 71% / 48 regs no-spill / 40 warps/SM).
// Empirically validated optimum after 14 rounds: float4 width, 256x5 launch
// bounds (only no-spill 48-reg config), two-phase body with Q front-loaded,
// ternary-predicated loads for pc/prior (any other load form regresses),
// __ldcs on single-use streams (Q,Qw,Tm,Phi) to keep the L2 reuse set
// (pressure/perm0/ws) resident, __stcs stores, guardless exact grid.
// Shapes: [B=8, T=10, NZ=4, NX=128, NY=128], y contiguous.
// d_out: [p_loss (N floats) | s_loss (N floats)], N = 5,242,880.

#define TS4 16384       // (4*128*128)/4
#define NV  32          // float4 vectors per row

__global__ __launch_bounds__(256, 5)
void blackoil_kernel_final(const float4* __restrict__ pr4,
                           const float4* __restrict__ perm4,
                           const float4* __restrict__ Q4,
                           const float4* __restrict__ Qw4,
                           const float4* __restrict__ Tm4,
                           const float4* __restrict__ Phi4,
                           const float* __restrict__ Swini,
                           const float4* __restrict__ ws4,
                           float4* __restrict__ out4,
                           int N4)
{
    const int v = blockIdx.x * blockDim.x + threadIdx.x;   // grid == N4 exactly

    const int y4 = v & (NV - 1);
    const int x  = (v >> 5) & 127;
    const int t  = (v >> 14) % 10;
    const int v0 = v - t * TS4;

    const int oxm = (x > 0)   ? -NV : 0;
    const int oxp = (x < 127) ?  NV : 0;

    const float* pr   = (const float*)pr4;
    const float* perm = (const float*)perm4;

    const float s0 = Swini[0];
    const float S0 = (s0 - 0.1f) * 1.25f;
    const float cW = S0 * S0;
    const float cM = cW + (1.0f - S0) * (1.0f - S0) * (1.0f / 2.75f);

    // ---------- phase 1 loads (issued up front, incl. streaming Q) ----------
    const float4 uc4  = pr4[v];
    const float4 uxm4 = pr4[v + oxm];
    const float4 uxp4 = pr4[v + oxp];
    const float4 p0c  = perm4[v0];
    const float4 p0xm = perm4[v0 + oxm];
    const float4 p0xp = perm4[v0 + oxp];
    const float4 q4   = __ldcs(&Q4[v]);          // single-use stream
    const float4 sat4 = ws4[v];
    const float4 pc     = (t == 0) ? p0c : perm4[v];
    const float4 prior4 = (t == 0) ? make_float4(s0, s0, s0, s0)
                                   : ws4[v - TS4];
    const float  uL = (y4 == 0)      ? uc4.x : pr[4 * v - 1];
    const float  uR = (y4 == NV - 1) ? uc4.w : pr[4 * v + 4];
    const float  pL = (y4 == 0)      ? p0c.x : perm[4 * v0 - 1];
    const float  pR = (y4 == NV - 1) ? p0c.w : perm[4 * v0 + 4];

    const float sc = 7.8125e-8f;   // (1/128)*1e-5

    float flux[4], dsw[4];

    {
        const float ucA[6]  = {uL, uc4.x, uc4.y, uc4.z, uc4.w, uR};
        const float pcA[6]  = {pL, p0c.x, p0c.y, p0c.z, p0c.w, pR};
        const float uxmA[4] = {uxm4.x, uxm4.y, uxm4.z, uxm4.w};
        const float uxpA[4] = {uxp4.x, uxp4.y, uxp4.z, uxp4.w};
        const float pxmA[4] = {p0xm.x, p0xm.y, p0xm.z, p0xm.w};
        const float pxpA[4] = {p0xp.x, p0xp.y, p0xp.z, p0xp.w};
        const float prA[4]  = {prior4.x, prior4.y, prior4.z, prior4.w};
        const float pmA[4]  = {pc.x, pc.y, pc.z, pc.w};
        const float stA[4]  = {sat4.x, sat4.y, sat4.z, sat4.w};
        const float qA[4]   = {q4.x, q4.y, q4.z, q4.w};

        float pl[4];

        #pragma unroll
        for (int i = 0; i < 4; i++) {
            // u = p*1000, h = 1/128
            const float uc   = ucA[i + 1];
            const float dudx = (uxpA[i] - uxmA[i]) * 64000.0f;
            const float dudy = (ucA[i + 2] - ucA[i]) * 64000.0f;
            const float lap  = ((uxpA[i] - 2.0f * uc + uxmA[i])
                              + (ucA[i + 2] - 2.0f * uc + ucA[i])) * 16384000.0f;

            // a = 500*perm
            const float da0dx = (pxpA[i] - pxmA[i]) * 32000.0f;
            const float da0dy = (pcA[i + 2] - pcA[i]) * 32000.0f;
            const float t1 = da0dx * dudx + da0dy * dudy;

            const float prior = prA[i];
            const float S  = (prior - 0.1f) * 1.25f;
            const float Mw = S * S;
            const float Mo = (1.0f - S) * (1.0f - S) * (1.0f / 2.75f);
            const float aP = 500.0f * pmA[i];

            pl[i]   = sc * (qA[i] * 5000.0f + cM * t1 + (Mw + Mo) * aP * lap);
            flux[i] = cW * t1 + Mw * aP * lap;
            dsw[i]  = fmaxf(stA[i] - prior, 0.001f);
        }

        __stcs(&out4[v], make_float4(pl[0], pl[1], pl[2], pl[3]));
    }

    // ---------- phase 2: s_loss (all single-use streams) ----------
    {
        const float4 qw4 = __ldcs(&Qw4[v]);
        const float4 tm4 = __ldcs(&Tm4[v]);
        const float4 ph4 = __ldcs(&Phi4[v]);
        float4 sl;
        sl.x = sc * (ph4.x * (dsw[0] / (tm4.x * 6000.0f)) - (flux[0] + qw4.x * 5000.0f));
        sl.y = sc * (ph4.y * (dsw[1] / (tm4.y * 6000.0f)) - (flux[1] + qw4.y * 5000.0f));
        sl.z = sc * (ph4.z * (dsw[2] / (tm4.z * 6000.0f)) - (flux[2] + qw4.z * 5000.0f));
        sl.w = sc * (ph4.w * (dsw[3] / (tm4.w * 6000.0f)) - (flux[3] + qw4.w * 5000.0f));
        __stcs(&out4[N4 + v], sl);
    }
}

extern "C" void kernel_launch(void* const* d_in, const int* in_sizes, int n_in,
                              void* d_out, int out_size)
{
    const float4* pressure = (const float4*)d_in[0];
    const float4* perm     = (const float4*)d_in[1];
    const float4* Q        = (const float4*)d_in[2];
    const float4* Qw       = (const float4*)d_in[3];
    const float4* Time     = (const float4*)d_in[4];
    // d_in[5] = Pini — unused
    const float4* Phi      = (const float4*)d_in[6];
    const float*  Swini    = (const float*)d_in[7];
    const float4* wsat     = (const float4*)d_in[8];
    float4* out = (float4*)d_out;

    const int N4 = in_sizes[0] / 4;      // 1,310,720 == 5120 * 256 exactly
    const int threads = 256;
    const int blocks = N4 / threads;     // exact division — no guard in kernel
    blackoil_kernel_final<<<blocks, threads>>>(pressure, perm, Q, Qw, Time, Phi,
                                               Swini, wsat, out, N4);
}

// round 16
// speedup vs baseline: 1.0092x; 1.0092x over previous
#include <cuda_runtime.h>

// Black_oil PINO residual, GB300 sm_103a — float4 over y.
// R16 = R8 (best: 27.8us ncu) with y-edge scalars (uL/uR/pL/pR) obtained via
// warp shuffle instead of 4 scalar LDGs: lane i holds y4=i, so the neighbor
// element lives in the adjacent lane's register; replicate-clamp at lanes
// 0/31 via select. Cuts memory instructions 16 -> 12 with no barrier and no
// extra registers. All other R8 forms unchanged: ternary plain loads for
// pc/prior, __ldcs on single-use streams, __stcs stores, guardless grid.
// Shapes: [B=8, T=10, NZ=4, NX=128, NY=128], y contiguous.
// d_out: [p_loss (N floats) | s_loss (N floats)], N = 5,242,880.

#define TS4 16384       // (4*128*128)/4
#define NV  32          // float4 vectors per row

__global__ __launch_bounds__(256, 5)
void blackoil_kernel_v16(const float4* __restrict__ pr4,
                         const float4* __restrict__ perm4,
                         const float4* __restrict__ Q4,
                         const float4* __restrict__ Qw4,
                         const float4* __restrict__ Tm4,
                         const float4* __restrict__ Phi4,
                         const float* __restrict__ Swini,
                         const float4* __restrict__ ws4,
                         float4* __restrict__ out4,
                         int N4)
{
    const int v = blockIdx.x * blockDim.x + threadIdx.x;   // grid == N4 exactly

    const int lane = threadIdx.x & 31;     // == y4 (warps are y-row aligned)
    const int x  = (v >> 5) & 127;
    const int t  = (v >> 14) % 10;
    const int v0 = v - t * TS4;

    const int oxm = (x > 0)   ? -NV : 0;
    const int oxp = (x < 127) ?  NV : 0;

    const float s0 = Swini[0];
    const float S0 = (s0 - 0.1f) * 1.25f;
    const float cW = S0 * S0;
    const float cM = cW + (1.0f - S0) * (1.0f - S0) * (1.0f / 2.75f);

    // ---------- phase 1 loads (issued up front, incl. streaming Q) ----------
    const float4 uc4  = pr4[v];
    const float4 uxm4 = pr4[v + oxm];
    const float4 uxp4 = pr4[v + oxp];
    const float4 p0c  = perm4[v0];
    const float4 p0xm = perm4[v0 + oxm];
    const float4 p0xp = perm4[v0 + oxp];
    const float4 q4   = __ldcs(&Q4[v]);          // single-use stream
    const float4 sat4 = ws4[v];
    const float4 pc     = (t == 0) ? p0c : perm4[v];
    const float4 prior4 = (t == 0) ? make_float4(s0, s0, s0, s0)
                                   : ws4[v - TS4];

    // ---------- y-edge neighbors via warp shuffle (no LDG) ----------
    // lane i holds y-vec i; left scalar = lane i-1's .w, right = lane i+1's .x.
    // Replicate clamp at lane 0 (y==0) and lane 31 (y==127).
    const float uLs = __shfl_up_sync(0xFFFFFFFFu,  uc4.w, 1);
    const float uRs = __shfl_down_sync(0xFFFFFFFFu, uc4.x, 1);
    const float pLs = __shfl_up_sync(0xFFFFFFFFu,  p0c.w, 1);
    const float pRs = __shfl_down_sync(0xFFFFFFFFu, p0c.x, 1);
    const float uL = (lane == 0)  ? uc4.x : uLs;
    const float uR = (lane == 31) ? uc4.w : uRs;
    const float pL = (lane == 0)  ? p0c.x : pLs;
    const float pR = (lane == 31) ? p0c.w : pRs;

    const float sc = 7.8125e-8f;   // (1/128)*1e-5

    float flux[4], dsw[4];

    {
        const float ucA[6]  = {uL, uc4.x, uc4.y, uc4.z, uc4.w, uR};
        const float pcA[6]  = {pL, p0c.x, p0c.y, p0c.z, p0c.w, pR};
        const float uxmA[4] = {uxm4.x, uxm4.y, uxm4.z, uxm4.w};
        const float uxpA[4] = {uxp4.x, uxp4.y, uxp4.z, uxp4.w};
        const float pxmA[4] = {p0xm.x, p0xm.y, p0xm.z, p0xm.w};
        const float pxpA[4] = {p0xp.x, p0xp.y, p0xp.z, p0xp.w};
        const float prA[4]  = {prior4.x, prior4.y, prior4.z, prior4.w};
        const float pmA[4]  = {pc.x, pc.y, pc.z, pc.w};
        const float stA[4]  = {sat4.x, sat4.y, sat4.z, sat4.w};
        const float qA[4]   = {q4.x, q4.y, q4.z, q4.w};

        float pl[4];

        #pragma unroll
        for (int i = 0; i < 4; i++) {
            // u = p*1000, h = 1/128
            const float uc   = ucA[i + 1];
            const float dudx = (uxpA[i] - uxmA[i]) * 64000.0f;
            const float dudy = (ucA[i + 2] - ucA[i]) * 64000.0f;
            const float lap  = ((uxpA[i] - 2.0f * uc + uxmA[i])
                              + (ucA[i + 2] - 2.0f * uc + ucA[i])) * 16384000.0f;

            // a = 500*perm
            const float da0dx = (pxpA[i] - pxmA[i]) * 32000.0f;
            const float da0dy = (pcA[i + 2] - pcA[i]) * 32000.0f;
            const float t1 = da0dx * dudx + da0dy * dudy;

            const float prior = prA[i];
            const float S  = (prior - 0.1f) * 1.25f;
            const float Mw = S * S;
            const float Mo = (1.0f - S) * (1.0f - S) * (1.0f / 2.75f);
            const float aP = 500.0f * pmA[i];

            pl[i]   = sc * (qA[i] * 5000.0f + cM * t1 + (Mw + Mo) * aP * lap);
            flux[i] = cW * t1 + Mw * aP * lap;
            dsw[i]  = fmaxf(stA[i] - prior, 0.001f);
        }

        __stcs(&out4[v], make_float4(pl[0], pl[1], pl[2], pl[3]));
    }

    // ---------- phase 2: s_loss (all single-use streams) ----------
    {
        const float4 qw4 = __ldcs(&Qw4[v]);
        const float4 tm4 = __ldcs(&Tm4[v]);
        const float4 ph4 = __ldcs(&Phi4[v]);
        float4 sl;
        sl.x = sc * (ph4.x * (dsw[0] / (tm4.x * 6000.0f)) - (flux[0] + qw4.x * 5000.0f));
        sl.y = sc * (ph4.y * (dsw[1] / (tm4.y * 6000.0f)) - (flux[1] + qw4.y * 5000.0f));
        sl.z = sc * (ph4.z * (dsw[2] / (tm4.z * 6000.0f)) - (flux[2] + qw4.z * 5000.0f));
        sl.w = sc * (ph4.w * (dsw[3] / (tm4.w * 6000.0f)) - (flux[3] + qw4.w * 5000.0f));
        __stcs(&out4[N4 + v], sl);
    }
}

extern "C" void kernel_launch(void* const* d_in, const int* in_sizes, int n_in,
                              void* d_out, int out_size)
{
    const float4* pressure = (const float4*)d_in[0];
    const float4* perm     = (const float4*)d_in[1];
    const float4* Q        = (const float4*)d_in[2];
    const float4* Qw       = (const float4*)d_in[3];
    const float4* Time     = (const float4*)d_in[4];
    // d_in[5] = Pini — unused
    const float4* Phi      = (const float4*)d_in[6];
    const float*  Swini    = (const float*)d_in[7];
    const float4* wsat     = (const float4*)d_in[8];
    float4* out = (float4*)d_out;

    const int N4 = in_sizes[0] / 4;      // 1,310,720 == 5120 * 256 exactly
    const int threads = 256;
    const int blocks = N4 / threads;     // exact division — no guard in kernel
    blackoil_kernel_v16<<<blocks, threads>>>(pressure, perm, Q, Qw, Time, Phi,
                                             Swini, wsat, out, N4);
}

// round 17
// speedup vs baseline: 1.0801x; 1.0703x over previous
#include <cuda_runtime.h>

// Black_oil PINO residual, GB300 sm_103a — float4 over y. FINAL.
// = R16 (plateau-equal with R8: 27.8-28.5us ncu, DRAM ~70%, 48 regs,
// 40 warps/SM) + __fdividef in the s_loss tail (4 MUFU-fast divides; rel_err
// budget 1e-3, measured ~1e-7).
// Validated forms: float4 width, (256,5) launch bounds (only no-spill 48-reg
// config), two-phase body, ternary-predicated pc/prior loads, y-edge scalars
// via warp shuffle (no LDG), __ldcs on single-use streams (Q,Qw,Tm,Phi),
// __stcs stores, guardless exact grid.
// Shapes: [B=8, T=10, NZ=4, NX=128, NY=128], y contiguous.
// d_out: [p_loss (N floats) | s_loss (N floats)], N = 5,242,880.

#define TS4 16384       // (4*128*128)/4
#define NV  32          // float4 vectors per row

__global__ __launch_bounds__(256, 5)
void blackoil_kernel_v17(const float4* __restrict__ pr4,
                         const float4* __restrict__ perm4,
                         const float4* __restrict__ Q4,
                         const float4* __restrict__ Qw4,
                         const float4* __restrict__ Tm4,
                         const float4* __restrict__ Phi4,
                         const float* __restrict__ Swini,
                         const float4* __restrict__ ws4,
                         float4* __restrict__ out4,
                         int N4)
{
    const int v = blockIdx.x * blockDim.x + threadIdx.x;   // grid == N4 exactly

    const int lane = threadIdx.x & 31;     // == y4 (warps are y-row aligned)
    const int x  = (v >> 5) & 127;
    const int t  = (v >> 14) % 10;
    const int v0 = v - t * TS4;

    const int oxm = (x > 0)   ? -NV : 0;
    const int oxp = (x < 127) ?  NV : 0;

    const float s0 = Swini[0];
    const float S0 = (s0 - 0.1f) * 1.25f;
    const float cW = S0 * S0;
    const float cM = cW + (1.0f - S0) * (1.0f - S0) * (1.0f / 2.75f);

    // ---------- phase 1 loads (issued up front, incl. streaming Q) ----------
    const float4 uc4  = pr4[v];
    const float4 uxm4 = pr4[v + oxm];
    const float4 uxp4 = pr4[v + oxp];
    const float4 p0c  = perm4[v0];
    const float4 p0xm = perm4[v0 + oxm];
    const float4 p0xp = perm4[v0 + oxp];
    const float4 q4   = __ldcs(&Q4[v]);          // single-use stream
    const float4 sat4 = ws4[v];
    const float4 pc     = (t == 0) ? p0c : perm4[v];
    const float4 prior4 = (t == 0) ? make_float4(s0, s0, s0, s0)
                                   : ws4[v - TS4];

    // ---------- y-edge neighbors via warp shuffle (no LDG) ----------
    const float uLs = __shfl_up_sync(0xFFFFFFFFu,  uc4.w, 1);
    const float uRs = __shfl_down_sync(0xFFFFFFFFu, uc4.x, 1);
    const float pLs = __shfl_up_sync(0xFFFFFFFFu,  p0c.w, 1);
    const float pRs = __shfl_down_sync(0xFFFFFFFFu, p0c.x, 1);
    const float uL = (lane == 0)  ? uc4.x : uLs;   // replicate clamp at y==0
    const float uR = (lane == 31) ? uc4.w : uRs;   // replicate clamp at y==127
    const float pL = (lane == 0)  ? p0c.x : pLs;
    const float pR = (lane == 31) ? p0c.w : pRs;

    const float sc = 7.8125e-8f;   // (1/128)*1e-5

    float flux[4], dsw[4];

    {
        const float ucA[6]  = {uL, uc4.x, uc4.y, uc4.z, uc4.w, uR};
        const float pcA[6]  = {pL, p0c.x, p0c.y, p0c.z, p0c.w, pR};
        const float uxmA[4] = {uxm4.x, uxm4.y, uxm4.z, uxm4.w};
        const float uxpA[4] = {uxp4.x, uxp4.y, uxp4.z, uxp4.w};
        const float pxmA[4] = {p0xm.x, p0xm.y, p0xm.z, p0xm.w};
        const float pxpA[4] = {p0xp.x, p0xp.y, p0xp.z, p0xp.w};
        const float prA[4]  = {prior4.x, prior4.y, prior4.z, prior4.w};
        const float pmA[4]  = {pc.x, pc.y, pc.z, pc.w};
        const float stA[4]  = {sat4.x, sat4.y, sat4.z, sat4.w};
        const float qA[4]   = {q4.x, q4.y, q4.z, q4.w};

        float pl[4];

        #pragma unroll
        for (int i = 0; i < 4; i++) {
            // u = p*1000, h = 1/128
            const float uc   = ucA[i + 1];
            const float dudx = (uxpA[i] - uxmA[i]) * 64000.0f;
            const float dudy = (ucA[i + 2] - ucA[i]) * 64000.0f;
            const float lap  = ((uxpA[i] - 2.0f * uc + uxmA[i])
                              + (ucA[i + 2] - 2.0f * uc + ucA[i])) * 16384000.0f;

            // a = 500*perm
            const float da0dx = (pxpA[i] - pxmA[i]) * 32000.0f;
            const float da0dy = (pcA[i + 2] - pcA[i]) * 32000.0f;
            const float t1 = da0dx * dudx + da0dy * dudy;

            const float prior = prA[i];
            const float S  = (prior - 0.1f) * 1.25f;
            const float Mw = S * S;
            const float Mo = (1.0f - S) * (1.0f - S) * (1.0f / 2.75f);
            const float aP = 500.0f * pmA[i];

            pl[i]   = sc * (qA[i] * 5000.0f + cM * t1 + (Mw + Mo) * aP * lap);
            flux[i] = cW * t1 + Mw * aP * lap;
            dsw[i]  = fmaxf(stA[i] - prior, 0.001f);
        }

        __stcs(&out4[v], make_float4(pl[0], pl[1], pl[2], pl[3]));
    }

    // ---------- phase 2: s_loss (single-use streams, fast divide) ----------
    {
        const float4 qw4 = __ldcs(&Qw4[v]);
        const float4 tm4 = __ldcs(&Tm4[v]);
        const float4 ph4 = __ldcs(&Phi4[v]);
        float4 sl;
        sl.x = sc * (ph4.x * __fdividef(dsw[0], tm4.x * 6000.0f) - (flux[0] + qw4.x * 5000.0f));
        sl.y = sc * (ph4.y * __fdividef(dsw[1], tm4.y * 6000.0f) - (flux[1] + qw4.y * 5000.0f));
        sl.z = sc * (ph4.z * __fdividef(dsw[2], tm4.z * 6000.0f) - (flux[2] + qw4.z * 5000.0f));
        sl.w = sc * (ph4.w * __fdividef(dsw[3], tm4.w * 6000.0f) - (flux[3] + qw4.w * 5000.0f));
        __stcs(&out4[N4 + v], sl);
    }
}

extern "C" void kernel_launch(void* const* d_in, const int* in_sizes, int n_in,
                              void* d_out, int out_size)
{
    const float4* pressure = (const float4*)d_in[0];
    const float4* perm     = (const float4*)d_in[1];
    const float4* Q        = (const float4*)d_in[2];
    const float4* Qw       = (const float4*)d_in[3];
    const float4* Time     = (const float4*)d_in[4];
    // d_in[5] = Pini — unused
    const float4* Phi      = (const float4*)d_in[6];
    const float*  Swini    = (const float*)d_in[7];
    const float4* wsat     = (const float4*)d_in[8];
    float4* out = (float4*)d_out;

    const int N4 = in_sizes[0] / 4;      // 1,310,720 == 5120 * 256 exactly
    const int threads = 256;
    const int blocks = N4 / threads;     // exact division — no guard in kernel
    blackoil_kernel_v17<<<blocks, threads>>>(pressure, perm, Q, Qw, Time, Phi,
                                             Swini, wsat, out, N4);
}